// round 7
// baseline (speedup 1.0000x reference)
#include <cuda_runtime.h>
#include <math.h>

// ---------------------------------------------------------------------------
// QuantumNATHybrid — fused persistent kernel v4.
//   R5-proven pooling (warp-per-image) staged to shared -> thread-per-image
//   quadratic form + MLP (shared weights) -> write out -> grid barrier ->
//   stats (doubles, last block) -> in-place batchnorm.  All sums fixed-order.
// ---------------------------------------------------------------------------

__device__ float g_partials[1024 * 8];
__device__ float g_mu[4];
__device__ float g_rstd[4];
__device__ unsigned g_arrive = 0;     // reset by last block each launch
__device__ unsigned g_release = 0;    // monotonic generation counter

__device__ __forceinline__ float cz_sign(int i) {
    int b0 = (i >> 3) & 1, b1 = (i >> 2) & 1, b2 = (i >> 1) & 1, b3 = i & 1;
    int s = (b0 & b1) + (b1 & b2) + (b2 & b3) + (b3 & b0);
    return (s & 1) ? -1.0f : 1.0f;
}

__global__ void __launch_bounds__(256, 2) fused_kernel(
    const float* __restrict__ x,
    const float* __restrict__ qw,
    const float* __restrict__ w1, const float* __restrict__ b1,
    const float* __restrict__ w2, const float* __restrict__ b2,
    const float* __restrict__ gamma, const float* __restrict__ beta,
    float* __restrict__ out, int Bn)
{
    __shared__ float  sr[4][16], si[4][16];
    __shared__ float  sA[64];          // [w][j][k]
    __shared__ float4 sW1[64];         // per-hidden j: (w1[0][j],..,w1[3][j])
    __shared__ float4 sW2[64];         // w2 rows
    __shared__ float  sB1[64];
    __shared__ float  sb2[4];
    __shared__ float4 s_s[256];        // pooled s-vectors
    __shared__ float  w8[8][8];
    __shared__ double red[256];
    __shared__ unsigned s_islast, s_gen;

    int tid  = threadIdx.x;
    int lane = tid & 31;
    int wrp  = tid >> 5;

    // ===== Phase 0a: circuit sim (warp 0) || weight staging (warps 2..6) ===
    if (wrp == 0) {
        int j = tid >> 3;   // basis column 0..3
        int p = tid & 7;    // amplitude pair 0..7
        int ia = 2 * p, ib = 2 * p + 1;
        sr[j][ia] = (ia == j) ? 1.0f : 0.0f;  si[j][ia] = 0.0f;
        sr[j][ib] = (ib == j) ? 1.0f : 0.0f;  si[j][ib] = 0.0f;
        __syncwarp();
        for (int l = 0; l < 2; l++) {
            for (int wq = 0; wq < 4; wq++) {
                int R  = 1 << (3 - wq);
                int i0 = ((p & ~(R - 1)) << 1) | (p & (R - 1));
                int i1 = i0 | R;
                float r0 = sr[j][i0], m0 = si[j][i0];
                float r1 = sr[j][i1], m1 = si[j][i1];
                const float* a = qw + (l * 4 + wq) * 3;
                float c, s, nr0, ni0, nr1, ni1;
                // RX: [[c,-is],[-is,c]]
                sincosf(0.5f * a[0], &s, &c);
                nr0 = c*r0 + s*m1;  ni0 = c*m0 - s*r1;
                nr1 = s*m0 + c*r1;  ni1 = -s*r0 + c*m1;
                r0 = nr0; m0 = ni0; r1 = nr1; m1 = ni1;
                // RY: [[c,-s],[s,c]]
                sincosf(0.5f * a[1], &s, &c);
                nr0 = c*r0 - s*r1;  ni0 = c*m0 - s*m1;
                nr1 = s*r0 + c*r1;  ni1 = s*m0 + c*m1;
                r0 = nr0; m0 = ni0; r1 = nr1; m1 = ni1;
                // RZ: diag(c-is, c+is)
                sincosf(0.5f * a[2], &s, &c);
                nr0 = c*r0 + s*m0;  ni0 = c*m0 - s*r0;
                nr1 = c*r1 - s*m1;  ni1 = c*m1 + s*r1;
                r0 = nr0; m0 = ni0; r1 = nr1; m1 = ni1;
                if (wq == 3) {     // CZ ring (0,1)(1,2)(2,3)(3,0)
                    float s0 = cz_sign(i0), s1 = cz_sign(i1);
                    r0 *= s0; m0 *= s0; r1 *= s1; m1 *= s1;
                }
                sr[j][i0] = r0; si[j][i0] = m0;
                sr[j][i1] = r1; si[j][i1] = m1;
                __syncwarp();
            }
        }
    }
    if (tid >= 64 && tid < 128) {
        int i = tid - 64;
        sW1[i] = make_float4(w1[i], w1[64 + i], w1[128 + i], w1[192 + i]);
        sB1[i] = b1[i];
    }
    if (tid >= 128 && tid < 192) {
        int i = tid - 128;
        sW2[i] = ((const float4*)w2)[i];
    }
    if (tid >= 192 && tid < 196) sb2[tid - 192] = b2[tid - 192];
    __syncthreads();

    // ===== Phase 0b: A_w (threads 0..63) ===================================
    if (tid < 64) {
        int wq = tid >> 4, j = (tid >> 2) & 3, k = tid & 3;
        float acc = 0.0f;
#pragma unroll
        for (int i = 0; i < 16; i++) {
            float z = 1.0f - 2.0f * (float)((i >> (3 - wq)) & 1);
            acc += z * (sr[j][i] * sr[k][i] + si[j][i] * si[k][i]);
        }
        sA[tid] = acc;
    }
    __syncthreads();

    float as0 = 0.f, as1 = 0.f, as2 = 0.f, as3 = 0.f;
    float aq0 = 0.f, aq1 = 0.f, aq2 = 0.f, aq3 = 0.f;

    // ===== Main persistent loop: 256 images per block-iteration ============
    for (int base = blockIdx.x * 256; base < Bn; base += gridDim.x * 256) {

        // ----- pooling: warp wrp pools images wrp + 8k (R5-proven logic) ---
#pragma unroll 4
        for (int k = 0; k < 32; k++) {
            int imgl = wrp + 8 * k;
            int img  = base + imgl;
            float a0 = 0.f, a1 = 0.f, a2 = 0.f, a3 = 0.f;
            if (img < Bn) {
                const float4* p = (const float4*)(x + (size_t)img * 784);
#pragma unroll
                for (int it = 0; it < 2; it++) {
                    int t = lane + it * 32;
                    if (t < 42) {
                        float4 v = __ldcs(p + t);
                        float f[4] = { v.x, v.y, v.z, v.w };
#pragma unroll
                        for (int e = 0; e < 4; e++) {
                            int idx = 4 * t + e;
                            int col = idx - (idx / 28) * 28;
                            if (col < 24) {
                                if      (col <  6) a0 += f[e];
                                else if (col < 12) a1 += f[e];
                                else if (col < 18) a2 += f[e];
                                else               a3 += f[e];
                            }
                        }
                    }
                }
            }
#pragma unroll
            for (int off = 16; off; off >>= 1) {
                a0 += __shfl_xor_sync(0xffffffffu, a0, off);
                a1 += __shfl_xor_sync(0xffffffffu, a1, off);
                a2 += __shfl_xor_sync(0xffffffffu, a2, off);
                a3 += __shfl_xor_sync(0xffffffffu, a3, off);
            }
            if (lane == 0) s_s[imgl] = make_float4(a0, a1, a2, a3);
        }
        __syncthreads();

        // ----- compute: one thread per image -------------------------------
        int img = base + tid;
        if (img < Bn) {
            float4 svv = s_s[tid];
            float sv[4] = { svv.x, svv.y, svv.z, svv.w };
            float inv = 1.0f / (sv[0]*sv[0] + sv[1]*sv[1] +
                                sv[2]*sv[2] + sv[3]*sv[3]);
            float q0 = 0.f, q1 = 0.f, q2 = 0.f, q3 = 0.f;
#pragma unroll
            for (int jj = 0; jj < 4; jj++)
#pragma unroll
                for (int kk = 0; kk < 4; kk++) {
                    float p = sv[jj] * sv[kk];
                    q0 += sA[ 0 + jj * 4 + kk] * p;
                    q1 += sA[16 + jj * 4 + kk] * p;
                    q2 += sA[32 + jj * 4 + kk] * p;
                    q3 += sA[48 + jj * 4 + kk] * p;
                }
            q0 *= inv; q1 *= inv; q2 *= inv; q3 *= inv;

            float o0 = 0.f, o1 = 0.f, o2 = 0.f, o3 = 0.f;
#pragma unroll 8
            for (int j = 0; j < 64; j++) {
                float4 wv = sW1[j];
                float hv = sB1[j] + q0*wv.x + q1*wv.y + q2*wv.z + q3*wv.w;
                hv = fmaxf(hv, 0.f);
                float4 w2v = sW2[j];
                o0 += hv * w2v.x;  o1 += hv * w2v.y;
                o2 += hv * w2v.z;  o3 += hv * w2v.w;
            }
            float r0 = o0 + sb2[0], r1 = o1 + sb2[1];
            float r2 = o2 + sb2[2], r3 = o3 + sb2[3];
            ((float4*)out)[img] = make_float4(r0, r1, r2, r3);

            as0 += r0;      as1 += r1;      as2 += r2;      as3 += r3;
            aq0 += r0 * r0; aq1 += r1 * r1; aq2 += r2 * r2; aq3 += r3 * r3;
        }
        __syncthreads();   // s_s reused next iteration
    }

    // ===== block partial reduce (deterministic) ============================
#pragma unroll
    for (int off = 16; off; off >>= 1) {
        as0 += __shfl_xor_sync(0xffffffffu, as0, off);
        as1 += __shfl_xor_sync(0xffffffffu, as1, off);
        as2 += __shfl_xor_sync(0xffffffffu, as2, off);
        as3 += __shfl_xor_sync(0xffffffffu, as3, off);
        aq0 += __shfl_xor_sync(0xffffffffu, aq0, off);
        aq1 += __shfl_xor_sync(0xffffffffu, aq1, off);
        aq2 += __shfl_xor_sync(0xffffffffu, aq2, off);
        aq3 += __shfl_xor_sync(0xffffffffu, aq3, off);
    }
    if (lane == 0) {
        w8[wrp][0] = as0; w8[wrp][1] = as1; w8[wrp][2] = as2; w8[wrp][3] = as3;
        w8[wrp][4] = aq0; w8[wrp][5] = aq1; w8[wrp][6] = aq2; w8[wrp][7] = aq3;
    }
    __syncthreads();
    if (tid < 8) {
        float a = 0.f;
#pragma unroll
        for (int k = 0; k < 8; k++) a += w8[k][tid];
        g_partials[blockIdx.x * 8 + tid] = a;
    }
    __threadfence();

    // ===== software grid barrier; last block computes stats ================
    if (tid == 0) {
        unsigned gen = *(volatile unsigned*)&g_release;
        unsigned old = atomicAdd(&g_arrive, 1);
        s_islast = (old == gridDim.x - 1) ? 1u : 0u;
        s_gen = gen;
    }
    __syncthreads();

    if (s_islast) {
        int c = tid & 7, idx = tid >> 3;
        double a = 0.0;
        for (int i = idx; i < (int)gridDim.x; i += 32)
            a += (double)__ldcg(&g_partials[i * 8 + c]);
        red[tid] = a;
        __syncthreads();
        for (int off = 128; off >= 8; off >>= 1) {
            if (tid < off) red[tid] += red[tid + off];
            __syncthreads();
        }
        if (tid < 4) {
            double mu  = red[tid] / (double)Bn;
            double var = red[tid + 4] / (double)Bn - mu * mu;
            g_mu[tid]   = (float)mu;
            g_rstd[tid] = (float)(1.0 / sqrt(var + 1e-5));
        }
        __syncthreads();
        if (tid == 0) {
            g_arrive = 0;
            __threadfence();
            atomicAdd(&g_release, 1);
        }
    } else {
        if (tid == 0) {
            while (*(volatile unsigned*)&g_release == s_gen) { }
        }
        __syncthreads();
    }
    __threadfence();

    // ===== batchnorm: in-place, grid-stride ================================
    float mu0 = __ldcg(&g_mu[0]), mu1 = __ldcg(&g_mu[1]);
    float mu2 = __ldcg(&g_mu[2]), mu3 = __ldcg(&g_mu[3]);
    float rs0 = __ldcg(&g_rstd[0]), rs1 = __ldcg(&g_rstd[1]);
    float rs2 = __ldcg(&g_rstd[2]), rs3 = __ldcg(&g_rstd[3]);
    float gm0 = gamma[0], gm1 = gamma[1], gm2 = gamma[2], gm3 = gamma[3];
    float bt0 = beta[0],  bt1 = beta[1],  bt2 = beta[2],  bt3 = beta[3];

    for (int i = blockIdx.x * blockDim.x + tid; i < Bn;
         i += gridDim.x * blockDim.x) {
        float4 v = __ldcg(((const float4*)out) + i);
        v.x = (v.x - mu0) * rs0 * gm0 + bt0;
        v.y = (v.y - mu1) * rs1 * gm1 + bt1;
        v.z = (v.z - mu2) * rs2 * gm2 + bt2;
        v.w = (v.w - mu3) * rs3 * gm3 + bt3;
        ((float4*)out)[i] = v;
    }
}

extern "C" void kernel_launch(void* const* d_in, const int* in_sizes, int n_in,
                              void* d_out, int out_size) {
    const float* x     = (const float*)d_in[0];
    const float* qw    = (const float*)d_in[1];
    const float* w1    = (const float*)d_in[2];
    const float* b1    = (const float*)d_in[3];
    const float* w2    = (const float*)d_in[4];
    const float* b2    = (const float*)d_in[5];
    const float* gamma = (const float*)d_in[6];
    const float* beta  = (const float*)d_in[7];
    float* out = (float*)d_out;

    int Bn = in_sizes[0] / 784;             // 32768

    // Grid must be fully resident for the software barrier.
    int dev = 0, sms = 148, maxB = 1;
    cudaGetDevice(&dev);
    cudaDeviceGetAttribute(&sms, cudaDevAttrMultiProcessorCount, dev);
    cudaOccupancyMaxActiveBlocksPerMultiprocessor(&maxB, fused_kernel, 256, 0);
    if (maxB < 1) maxB = 1;
    long long cap = (long long)sms * maxB;
    long long ideal = (Bn + 255) / 256;     // 128 for Bn=32768
    long long grid = ideal;
    if (grid > cap)  grid = cap;
    if (grid > 1024) grid = 1024;           // g_partials capacity
    if (grid < 1)    grid = 1;

    fused_kernel<<<(int)grid, 256>>>(x, qw, w1, b1, w2, b2, gamma, beta,
                                     out, Bn);
}

// round 8
// speedup vs baseline: 1.9475x; 1.9475x over previous
#include <cuda_runtime.h>
#include <math.h>

// ---------------------------------------------------------------------------
// QuantumNATHybrid — fused persistent kernel v5.
//   v4 numerics (proven) at R5 occupancy: 64 images/block-iter, ~512 blocks,
//   <=64 regs for 4 blocks/SM residency.
//   pool (warp-per-image, R5-proven) -> thread-per-image quad form + MLP
//   (shared weights) -> write out -> grid barrier -> stats (doubles) ->
//   in-place batchnorm.  All sums fixed-order (deterministic).
// ---------------------------------------------------------------------------

#define IPB 64   // images per block-iteration

__device__ float g_partials[1024 * 8];
__device__ float g_mu[4];
__device__ float g_rstd[4];
__device__ unsigned g_arrive = 0;     // reset by last block each launch
__device__ unsigned g_release = 0;    // monotonic generation counter

__device__ __forceinline__ float cz_sign(int i) {
    int b0 = (i >> 3) & 1, b1 = (i >> 2) & 1, b2 = (i >> 1) & 1, b3 = i & 1;
    int s = (b0 & b1) + (b1 & b2) + (b2 & b3) + (b3 & b0);
    return (s & 1) ? -1.0f : 1.0f;
}

__global__ void __launch_bounds__(256, 4) fused_kernel(
    const float* __restrict__ x,
    const float* __restrict__ qw,
    const float* __restrict__ w1, const float* __restrict__ b1,
    const float* __restrict__ w2, const float* __restrict__ b2,
    const float* __restrict__ gamma, const float* __restrict__ beta,
    float* __restrict__ out, int Bn)
{
    __shared__ float  sr[4][16], si[4][16];
    __shared__ float  sA[64];          // [w][j][k]
    __shared__ float4 sW1[64];         // per-hidden j: (w1[0][j],..,w1[3][j])
    __shared__ float4 sW2[64];         // w2 rows
    __shared__ float  sB1[64];
    __shared__ float  sb2[4];
    __shared__ float4 s_s[IPB];        // pooled s-vectors
    __shared__ float  w8[8][8];
    __shared__ double red[256];
    __shared__ unsigned s_islast, s_gen;

    int tid  = threadIdx.x;
    int lane = tid & 31;
    int wrp  = tid >> 5;

    // ===== Phase 0a: circuit sim (warp 0) || weight staging (warps 2..6) ===
    if (wrp == 0) {
        int j = tid >> 3;   // basis column 0..3
        int p = tid & 7;    // amplitude pair 0..7
        int ia = 2 * p, ib = 2 * p + 1;
        sr[j][ia] = (ia == j) ? 1.0f : 0.0f;  si[j][ia] = 0.0f;
        sr[j][ib] = (ib == j) ? 1.0f : 0.0f;  si[j][ib] = 0.0f;
        __syncwarp();
        for (int l = 0; l < 2; l++) {
            for (int wq = 0; wq < 4; wq++) {
                int R  = 1 << (3 - wq);
                int i0 = ((p & ~(R - 1)) << 1) | (p & (R - 1));
                int i1 = i0 | R;
                float r0 = sr[j][i0], m0 = si[j][i0];
                float r1 = sr[j][i1], m1 = si[j][i1];
                const float* a = qw + (l * 4 + wq) * 3;
                float c, s, nr0, ni0, nr1, ni1;
                // RX: [[c,-is],[-is,c]]
                sincosf(0.5f * a[0], &s, &c);
                nr0 = c*r0 + s*m1;  ni0 = c*m0 - s*r1;
                nr1 = s*m0 + c*r1;  ni1 = -s*r0 + c*m1;
                r0 = nr0; m0 = ni0; r1 = nr1; m1 = ni1;
                // RY: [[c,-s],[s,c]]
                sincosf(0.5f * a[1], &s, &c);
                nr0 = c*r0 - s*r1;  ni0 = c*m0 - s*m1;
                nr1 = s*r0 + c*r1;  ni1 = s*m0 + c*m1;
                r0 = nr0; m0 = ni0; r1 = nr1; m1 = ni1;
                // RZ: diag(c-is, c+is)
                sincosf(0.5f * a[2], &s, &c);
                nr0 = c*r0 + s*m0;  ni0 = c*m0 - s*r0;
                nr1 = c*r1 - s*m1;  ni1 = c*m1 + s*r1;
                r0 = nr0; m0 = ni0; r1 = nr1; m1 = ni1;
                if (wq == 3) {     // CZ ring (0,1)(1,2)(2,3)(3,0)
                    float s0 = cz_sign(i0), s1 = cz_sign(i1);
                    r0 *= s0; m0 *= s0; r1 *= s1; m1 *= s1;
                }
                sr[j][i0] = r0; si[j][i0] = m0;
                sr[j][i1] = r1; si[j][i1] = m1;
                __syncwarp();
            }
        }
    }
    if (tid >= 64 && tid < 128) {
        int i = tid - 64;
        sW1[i] = make_float4(w1[i], w1[64 + i], w1[128 + i], w1[192 + i]);
        sB1[i] = b1[i];
    }
    if (tid >= 128 && tid < 192) {
        int i = tid - 128;
        sW2[i] = ((const float4*)w2)[i];
    }
    if (tid >= 192 && tid < 196) sb2[tid - 192] = b2[tid - 192];
    __syncthreads();

    // ===== Phase 0b: A_w (threads 0..63) ===================================
    if (tid < 64) {
        int wq = tid >> 4, j = (tid >> 2) & 3, k = tid & 3;
        float acc = 0.0f;
#pragma unroll
        for (int i = 0; i < 16; i++) {
            float z = 1.0f - 2.0f * (float)((i >> (3 - wq)) & 1);
            acc += z * (sr[j][i] * sr[k][i] + si[j][i] * si[k][i]);
        }
        sA[tid] = acc;
    }
    __syncthreads();

    float as0 = 0.f, as1 = 0.f, as2 = 0.f, as3 = 0.f;
    float aq0 = 0.f, aq1 = 0.f, aq2 = 0.f, aq3 = 0.f;

    // ===== Main persistent loop: IPB images per block-iteration ============
    for (int base = blockIdx.x * IPB; base < Bn; base += gridDim.x * IPB) {

        // ----- pooling: warp wrp pools images wrp + 8k (R5-proven logic) ---
#pragma unroll 2
        for (int k = 0; k < IPB / 8; k++) {
            int imgl = wrp + 8 * k;
            int img  = base + imgl;
            float a0 = 0.f, a1 = 0.f, a2 = 0.f, a3 = 0.f;
            if (img < Bn) {
                const float4* p = (const float4*)(x + (size_t)img * 784);
#pragma unroll
                for (int it = 0; it < 2; it++) {
                    int t = lane + it * 32;
                    if (t < 42) {
                        float4 v = __ldcs(p + t);
                        float f[4] = { v.x, v.y, v.z, v.w };
#pragma unroll
                        for (int e = 0; e < 4; e++) {
                            int idx = 4 * t + e;
                            int col = idx - (idx / 28) * 28;
                            if (col < 24) {
                                if      (col <  6) a0 += f[e];
                                else if (col < 12) a1 += f[e];
                                else if (col < 18) a2 += f[e];
                                else               a3 += f[e];
                            }
                        }
                    }
                }
            }
#pragma unroll
            for (int off = 16; off; off >>= 1) {
                a0 += __shfl_xor_sync(0xffffffffu, a0, off);
                a1 += __shfl_xor_sync(0xffffffffu, a1, off);
                a2 += __shfl_xor_sync(0xffffffffu, a2, off);
                a3 += __shfl_xor_sync(0xffffffffu, a3, off);
            }
            if (lane == 0) s_s[imgl] = make_float4(a0, a1, a2, a3);
        }
        __syncthreads();

        // ----- compute: one thread per image (threads 0..IPB-1) ------------
        int img = base + tid;
        if (tid < IPB && img < Bn) {
            float4 svv = s_s[tid];
            float sv[4] = { svv.x, svv.y, svv.z, svv.w };
            float inv = 1.0f / (sv[0]*sv[0] + sv[1]*sv[1] +
                                sv[2]*sv[2] + sv[3]*sv[3]);
            float q0 = 0.f, q1 = 0.f, q2 = 0.f, q3 = 0.f;
#pragma unroll
            for (int jj = 0; jj < 4; jj++)
#pragma unroll
                for (int kk = 0; kk < 4; kk++) {
                    float p = sv[jj] * sv[kk];
                    q0 += sA[ 0 + jj * 4 + kk] * p;
                    q1 += sA[16 + jj * 4 + kk] * p;
                    q2 += sA[32 + jj * 4 + kk] * p;
                    q3 += sA[48 + jj * 4 + kk] * p;
                }
            q0 *= inv; q1 *= inv; q2 *= inv; q3 *= inv;

            float o0 = 0.f, o1 = 0.f, o2 = 0.f, o3 = 0.f;
#pragma unroll 4
            for (int j = 0; j < 64; j++) {
                float4 wv = sW1[j];
                float hv = sB1[j] + q0*wv.x + q1*wv.y + q2*wv.z + q3*wv.w;
                hv = fmaxf(hv, 0.f);
                float4 w2v = sW2[j];
                o0 += hv * w2v.x;  o1 += hv * w2v.y;
                o2 += hv * w2v.z;  o3 += hv * w2v.w;
            }
            float r0 = o0 + sb2[0], r1 = o1 + sb2[1];
            float r2 = o2 + sb2[2], r3 = o3 + sb2[3];
            ((float4*)out)[img] = make_float4(r0, r1, r2, r3);

            as0 += r0;      as1 += r1;      as2 += r2;      as3 += r3;
            aq0 += r0 * r0; aq1 += r1 * r1; aq2 += r2 * r2; aq3 += r3 * r3;
        }
        __syncthreads();   // s_s reused next iteration
    }

    // ===== block partial reduce (deterministic) ============================
#pragma unroll
    for (int off = 16; off; off >>= 1) {
        as0 += __shfl_xor_sync(0xffffffffu, as0, off);
        as1 += __shfl_xor_sync(0xffffffffu, as1, off);
        as2 += __shfl_xor_sync(0xffffffffu, as2, off);
        as3 += __shfl_xor_sync(0xffffffffu, as3, off);
        aq0 += __shfl_xor_sync(0xffffffffu, aq0, off);
        aq1 += __shfl_xor_sync(0xffffffffu, aq1, off);
        aq2 += __shfl_xor_sync(0xffffffffu, aq2, off);
        aq3 += __shfl_xor_sync(0xffffffffu, aq3, off);
    }
    if (lane == 0) {
        w8[wrp][0] = as0; w8[wrp][1] = as1; w8[wrp][2] = as2; w8[wrp][3] = as3;
        w8[wrp][4] = aq0; w8[wrp][5] = aq1; w8[wrp][6] = aq2; w8[wrp][7] = aq3;
    }
    __syncthreads();
    if (tid < 8) {
        float a = 0.f;
#pragma unroll
        for (int k = 0; k < 8; k++) a += w8[k][tid];
        g_partials[blockIdx.x * 8 + tid] = a;
    }
    __threadfence();

    // ===== software grid barrier; last block computes stats ================
    if (tid == 0) {
        unsigned gen = *(volatile unsigned*)&g_release;
        unsigned old = atomicAdd(&g_arrive, 1);
        s_islast = (old == gridDim.x - 1) ? 1u : 0u;
        s_gen = gen;
    }
    __syncthreads();

    if (s_islast) {
        int c = tid & 7, idx = tid >> 3;
        double a = 0.0;
        for (int i = idx; i < (int)gridDim.x; i += 32)
            a += (double)__ldcg(&g_partials[i * 8 + c]);
        red[tid] = a;
        __syncthreads();
        for (int off = 128; off >= 8; off >>= 1) {
            if (tid < off) red[tid] += red[tid + off];
            __syncthreads();
        }
        if (tid < 4) {
            double mu  = red[tid] / (double)Bn;
            double var = red[tid + 4] / (double)Bn - mu * mu;
            g_mu[tid]   = (float)mu;
            g_rstd[tid] = (float)(1.0 / sqrt(var + 1e-5));
        }
        __syncthreads();
        if (tid == 0) {
            g_arrive = 0;
            __threadfence();
            atomicAdd(&g_release, 1);
        }
    } else {
        if (tid == 0) {
            while (*(volatile unsigned*)&g_release == s_gen) { }
        }
        __syncthreads();
    }
    __threadfence();

    // ===== batchnorm: in-place, grid-stride ================================
    float mu0 = __ldcg(&g_mu[0]), mu1 = __ldcg(&g_mu[1]);
    float mu2 = __ldcg(&g_mu[2]), mu3 = __ldcg(&g_mu[3]);
    float rs0 = __ldcg(&g_rstd[0]), rs1 = __ldcg(&g_rstd[1]);
    float rs2 = __ldcg(&g_rstd[2]), rs3 = __ldcg(&g_rstd[3]);
    float gm0 = gamma[0], gm1 = gamma[1], gm2 = gamma[2], gm3 = gamma[3];
    float bt0 = beta[0],  bt1 = beta[1],  bt2 = beta[2],  bt3 = beta[3];

    for (int i = blockIdx.x * blockDim.x + tid; i < Bn;
         i += gridDim.x * blockDim.x) {
        float4 v = __ldcg(((const float4*)out) + i);
        v.x = (v.x - mu0) * rs0 * gm0 + bt0;
        v.y = (v.y - mu1) * rs1 * gm1 + bt1;
        v.z = (v.z - mu2) * rs2 * gm2 + bt2;
        v.w = (v.w - mu3) * rs3 * gm3 + bt3;
        ((float4*)out)[i] = v;
    }
}

extern "C" void kernel_launch(void* const* d_in, const int* in_sizes, int n_in,
                              void* d_out, int out_size) {
    const float* x     = (const float*)d_in[0];
    const float* qw    = (const float*)d_in[1];
    const float* w1    = (const float*)d_in[2];
    const float* b1    = (const float*)d_in[3];
    const float* w2    = (const float*)d_in[4];
    const float* b2    = (const float*)d_in[5];
    const float* gamma = (const float*)d_in[6];
    const float* beta  = (const float*)d_in[7];
    float* out = (float*)d_out;

    int Bn = in_sizes[0] / 784;             // 32768

    // Grid must be fully resident for the software barrier.
    int dev = 0, sms = 148, maxB = 1;
    cudaGetDevice(&dev);
    cudaDeviceGetAttribute(&sms, cudaDevAttrMultiProcessorCount, dev);
    cudaOccupancyMaxActiveBlocksPerMultiprocessor(&maxB, fused_kernel, 256, 0);
    if (maxB < 1) maxB = 1;
    long long cap = (long long)sms * maxB;
    long long ideal = (Bn + IPB - 1) / IPB; // 512 for Bn=32768
    long long grid = ideal;
    if (grid > cap)  grid = cap;
    if (grid > 1024) grid = 1024;           // g_partials capacity
    if (grid < 1)    grid = 1;

    fused_kernel<<<(int)grid, 256>>>(x, qw, w1, b1, w2, b2, gamma, beta,
                                     out, Bn);
}

// round 9
// speedup vs baseline: 2.8121x; 1.4439x over previous
#include <cuda_runtime.h>
#include <math.h>

// ---------------------------------------------------------------------------
// QuantumNATHybrid — fused persistent kernel v6.
//   = v5 (proven @30.5us) + hoisted mask-based pair classification in pooling.
//   pool (warp-per-image) -> thread-per-image quad form + MLP (shared
//   weights) -> write out -> grid barrier -> stats (doubles) -> batchnorm.
// ---------------------------------------------------------------------------

#define IPB 64   // images per block-iteration

__device__ float g_partials[1024 * 8];
__device__ float g_mu[4];
__device__ float g_rstd[4];
__device__ unsigned g_arrive = 0;     // reset by last block each launch
__device__ unsigned g_release = 0;    // monotonic generation counter

__device__ __forceinline__ float cz_sign(int i) {
    int b0 = (i >> 3) & 1, b1 = (i >> 2) & 1, b2 = (i >> 1) & 1, b3 = i & 1;
    int s = (b0 & b1) + (b1 & b2) + (b2 & b3) + (b3 & b0);
    return (s & 1) ? -1.0f : 1.0f;
}

__global__ void __launch_bounds__(256, 4) fused_kernel(
    const float* __restrict__ x,
    const float* __restrict__ qw,
    const float* __restrict__ w1, const float* __restrict__ b1,
    const float* __restrict__ w2, const float* __restrict__ b2,
    const float* __restrict__ gamma, const float* __restrict__ beta,
    float* __restrict__ out, int Bn)
{
    __shared__ float  sr[4][16], si[4][16];
    __shared__ float  sA[64];          // [w][j][k]
    __shared__ float4 sW1[64];         // per-hidden j: (w1[0][j],..,w1[3][j])
    __shared__ float4 sW2[64];         // w2 rows
    __shared__ float  sB1[64];
    __shared__ float  sb2[4];
    __shared__ float4 s_s[IPB];        // pooled s-vectors
    __shared__ float  w8[8][8];
    __shared__ double red[256];
    __shared__ unsigned s_islast, s_gen;

    int tid  = threadIdx.x;
    int lane = tid & 31;
    int wrp  = tid >> 5;

    // ===== Phase 0a: circuit sim (warp 0) || weight staging ================
    if (wrp == 0) {
        int j = tid >> 3;   // basis column 0..3
        int p = tid & 7;    // amplitude pair 0..7
        int ia = 2 * p, ib = 2 * p + 1;
        sr[j][ia] = (ia == j) ? 1.0f : 0.0f;  si[j][ia] = 0.0f;
        sr[j][ib] = (ib == j) ? 1.0f : 0.0f;  si[j][ib] = 0.0f;
        __syncwarp();
        for (int l = 0; l < 2; l++) {
            for (int wq = 0; wq < 4; wq++) {
                int R  = 1 << (3 - wq);
                int i0 = ((p & ~(R - 1)) << 1) | (p & (R - 1));
                int i1 = i0 | R;
                float r0 = sr[j][i0], m0 = si[j][i0];
                float r1 = sr[j][i1], m1 = si[j][i1];
                const float* a = qw + (l * 4 + wq) * 3;
                float c, s, nr0, ni0, nr1, ni1;
                // RX: [[c,-is],[-is,c]]
                sincosf(0.5f * a[0], &s, &c);
                nr0 = c*r0 + s*m1;  ni0 = c*m0 - s*r1;
                nr1 = s*m0 + c*r1;  ni1 = -s*r0 + c*m1;
                r0 = nr0; m0 = ni0; r1 = nr1; m1 = ni1;
                // RY: [[c,-s],[s,c]]
                sincosf(0.5f * a[1], &s, &c);
                nr0 = c*r0 - s*r1;  ni0 = c*m0 - s*m1;
                nr1 = s*r0 + c*r1;  ni1 = s*m0 + c*m1;
                r0 = nr0; m0 = ni0; r1 = nr1; m1 = ni1;
                // RZ: diag(c-is, c+is)
                sincosf(0.5f * a[2], &s, &c);
                nr0 = c*r0 + s*m0;  ni0 = c*m0 - s*r0;
                nr1 = c*r1 - s*m1;  ni1 = c*m1 + s*r1;
                r0 = nr0; m0 = ni0; r1 = nr1; m1 = ni1;
                if (wq == 3) {     // CZ ring (0,1)(1,2)(2,3)(3,0)
                    float s0 = cz_sign(i0), s1 = cz_sign(i1);
                    r0 *= s0; m0 *= s0; r1 *= s1; m1 *= s1;
                }
                sr[j][i0] = r0; si[j][i0] = m0;
                sr[j][i1] = r1; si[j][i1] = m1;
                __syncwarp();
            }
        }
    }
    if (tid >= 64 && tid < 128) {
        int i = tid - 64;
        sW1[i] = make_float4(w1[i], w1[64 + i], w1[128 + i], w1[192 + i]);
        sB1[i] = b1[i];
    }
    if (tid >= 128 && tid < 192) {
        int i = tid - 128;
        sW2[i] = ((const float4*)w2)[i];
    }
    if (tid >= 192 && tid < 196) sb2[tid - 192] = b2[tid - 192];
    __syncthreads();

    // ===== Phase 0b: A_w (threads 0..63) ===================================
    if (tid < 64) {
        int wq = tid >> 4, j = (tid >> 2) & 3, k = tid & 3;
        float acc = 0.0f;
#pragma unroll
        for (int i = 0; i < 16; i++) {
            float z = 1.0f - 2.0f * (float)((i >> (3 - wq)) & 1);
            acc += z * (sr[j][i] * sr[k][i] + si[j][i] * si[k][i]);
        }
        sA[tid] = acc;
    }
    __syncthreads();

    // ===== Hoisted pooling classification masks (loop-invariant) ===========
    // float4 at index t covers cols c..c+3, c = (4t)%28 (never row-straddles
    // since 28%4==0).  Pairs (x+y),(z+w) start at even cols => never straddle
    // a 6-col block boundary.  One-hot masks per (it, pair, block).
    float msk[2][2][4];
#pragma unroll
    for (int it = 0; it < 2; it++) {
        int t = lane + 32 * it;
        int c = (4 * t) % 28;
        bool valid = (t < 42);
#pragma unroll
        for (int j = 0; j < 4; j++) {
            msk[it][0][j] = (valid && c     < 24 && (c     / 6) == j) ? 1.f : 0.f;
            msk[it][1][j] = (valid && c + 2 < 24 && ((c+2) / 6) == j) ? 1.f : 0.f;
        }
    }

    float as0 = 0.f, as1 = 0.f, as2 = 0.f, as3 = 0.f;
    float aq0 = 0.f, aq1 = 0.f, aq2 = 0.f, aq3 = 0.f;

    // ===== Main persistent loop: IPB images per block-iteration ============
    for (int base = blockIdx.x * IPB; base < Bn; base += gridDim.x * IPB) {

        // ----- pooling: warp wrp pools images wrp + 8k ---------------------
#pragma unroll 2
        for (int k = 0; k < IPB / 8; k++) {
            int imgl = wrp + 8 * k;
            int img  = base + imgl;
            float a0 = 0.f, a1 = 0.f, a2 = 0.f, a3 = 0.f;
            if (img < Bn) {
                const float4* p = (const float4*)(x + (size_t)img * 784);
#pragma unroll
                for (int it = 0; it < 2; it++) {
                    int t = lane + it * 32;
                    if (t < 42) {
                        float4 v = __ldcs(p + t);
                        float p0 = v.x + v.y, p1 = v.z + v.w;
                        a0 = fmaf(p0, msk[it][0][0], fmaf(p1, msk[it][1][0], a0));
                        a1 = fmaf(p0, msk[it][0][1], fmaf(p1, msk[it][1][1], a1));
                        a2 = fmaf(p0, msk[it][0][2], fmaf(p1, msk[it][1][2], a2));
                        a3 = fmaf(p0, msk[it][0][3], fmaf(p1, msk[it][1][3], a3));
                    }
                }
            }
#pragma unroll
            for (int off = 16; off; off >>= 1) {
                a0 += __shfl_xor_sync(0xffffffffu, a0, off);
                a1 += __shfl_xor_sync(0xffffffffu, a1, off);
                a2 += __shfl_xor_sync(0xffffffffu, a2, off);
                a3 += __shfl_xor_sync(0xffffffffu, a3, off);
            }
            if (lane == 0) s_s[imgl] = make_float4(a0, a1, a2, a3);
        }
        __syncthreads();

        // ----- compute: one thread per image (threads 0..IPB-1) ------------
        int img = base + tid;
        if (tid < IPB && img < Bn) {
            float4 svv = s_s[tid];
            float sv[4] = { svv.x, svv.y, svv.z, svv.w };
            float inv = 1.0f / (sv[0]*sv[0] + sv[1]*sv[1] +
                                sv[2]*sv[2] + sv[3]*sv[3]);
            float q0 = 0.f, q1 = 0.f, q2 = 0.f, q3 = 0.f;
#pragma unroll
            for (int jj = 0; jj < 4; jj++)
#pragma unroll
                for (int kk = 0; kk < 4; kk++) {
                    float p = sv[jj] * sv[kk];
                    q0 += sA[ 0 + jj * 4 + kk] * p;
                    q1 += sA[16 + jj * 4 + kk] * p;
                    q2 += sA[32 + jj * 4 + kk] * p;
                    q3 += sA[48 + jj * 4 + kk] * p;
                }
            q0 *= inv; q1 *= inv; q2 *= inv; q3 *= inv;

            float o0 = 0.f, o1 = 0.f, o2 = 0.f, o3 = 0.f;
#pragma unroll 4
            for (int j = 0; j < 64; j++) {
                float4 wv = sW1[j];
                float hv = sB1[j] + q0*wv.x + q1*wv.y + q2*wv.z + q3*wv.w;
                hv = fmaxf(hv, 0.f);
                float4 w2v = sW2[j];
                o0 += hv * w2v.x;  o1 += hv * w2v.y;
                o2 += hv * w2v.z;  o3 += hv * w2v.w;
            }
            float r0 = o0 + sb2[0], r1 = o1 + sb2[1];
            float r2 = o2 + sb2[2], r3 = o3 + sb2[3];
            ((float4*)out)[img] = make_float4(r0, r1, r2, r3);

            as0 += r0;      as1 += r1;      as2 += r2;      as3 += r3;
            aq0 += r0 * r0; aq1 += r1 * r1; aq2 += r2 * r2; aq3 += r3 * r3;
        }
        __syncthreads();   // s_s reused next iteration
    }

    // ===== block partial reduce (deterministic) ============================
#pragma unroll
    for (int off = 16; off; off >>= 1) {
        as0 += __shfl_xor_sync(0xffffffffu, as0, off);
        as1 += __shfl_xor_sync(0xffffffffu, as1, off);
        as2 += __shfl_xor_sync(0xffffffffu, as2, off);
        as3 += __shfl_xor_sync(0xffffffffu, as3, off);
        aq0 += __shfl_xor_sync(0xffffffffu, aq0, off);
        aq1 += __shfl_xor_sync(0xffffffffu, aq1, off);
        aq2 += __shfl_xor_sync(0xffffffffu, aq2, off);
        aq3 += __shfl_xor_sync(0xffffffffu, aq3, off);
    }
    if (lane == 0) {
        w8[wrp][0] = as0; w8[wrp][1] = as1; w8[wrp][2] = as2; w8[wrp][3] = as3;
        w8[wrp][4] = aq0; w8[wrp][5] = aq1; w8[wrp][6] = aq2; w8[wrp][7] = aq3;
    }
    __syncthreads();
    if (tid < 8) {
        float a = 0.f;
#pragma unroll
        for (int k = 0; k < 8; k++) a += w8[k][tid];
        g_partials[blockIdx.x * 8 + tid] = a;
    }
    __threadfence();

    // ===== software grid barrier; last block computes stats ================
    if (tid == 0) {
        unsigned gen = *(volatile unsigned*)&g_release;
        unsigned old = atomicAdd(&g_arrive, 1);
        s_islast = (old == gridDim.x - 1) ? 1u : 0u;
        s_gen = gen;
    }
    __syncthreads();

    if (s_islast) {
        int c = tid & 7, idx = tid >> 3;
        double a = 0.0;
        for (int i = idx; i < (int)gridDim.x; i += 32)
            a += (double)__ldcg(&g_partials[i * 8 + c]);
        red[tid] = a;
        __syncthreads();
        for (int off = 128; off >= 8; off >>= 1) {
            if (tid < off) red[tid] += red[tid + off];
            __syncthreads();
        }
        if (tid < 4) {
            double mu  = red[tid] / (double)Bn;
            double var = red[tid + 4] / (double)Bn - mu * mu;
            g_mu[tid]   = (float)mu;
            g_rstd[tid] = (float)(1.0 / sqrt(var + 1e-5));
        }
        __syncthreads();
        if (tid == 0) {
            g_arrive = 0;
            __threadfence();
            atomicAdd(&g_release, 1);
        }
    } else {
        if (tid == 0) {
            while (*(volatile unsigned*)&g_release == s_gen) { }
        }
        __syncthreads();
    }
    __threadfence();

    // ===== batchnorm: in-place, grid-stride ================================
    float mu0 = __ldcg(&g_mu[0]), mu1 = __ldcg(&g_mu[1]);
    float mu2 = __ldcg(&g_mu[2]), mu3 = __ldcg(&g_mu[3]);
    float rs0 = __ldcg(&g_rstd[0]), rs1 = __ldcg(&g_rstd[1]);
    float rs2 = __ldcg(&g_rstd[2]), rs3 = __ldcg(&g_rstd[3]);
    float gm0 = gamma[0], gm1 = gamma[1], gm2 = gamma[2], gm3 = gamma[3];
    float bt0 = beta[0],  bt1 = beta[1],  bt2 = beta[2],  bt3 = beta[3];

    for (int i = blockIdx.x * blockDim.x + tid; i < Bn;
         i += gridDim.x * blockDim.x) {
        float4 v = __ldcg(((const float4*)out) + i);
        v.x = (v.x - mu0) * rs0 * gm0 + bt0;
        v.y = (v.y - mu1) * rs1 * gm1 + bt1;
        v.z = (v.z - mu2) * rs2 * gm2 + bt2;
        v.w = (v.w - mu3) * rs3 * gm3 + bt3;
        ((float4*)out)[i] = v;
    }
}

extern "C" void kernel_launch(void* const* d_in, const int* in_sizes, int n_in,
                              void* d_out, int out_size) {
    const float* x     = (const float*)d_in[0];
    const float* qw    = (const float*)d_in[1];
    const float* w1    = (const float*)d_in[2];
    const float* b1    = (const float*)d_in[3];
    const float* w2    = (const float*)d_in[4];
    const float* b2    = (const float*)d_in[5];
    const float* gamma = (const float*)d_in[6];
    const float* beta  = (const float*)d_in[7];
    float* out = (float*)d_out;

    int Bn = in_sizes[0] / 784;             // 32768

    // Grid must be fully resident for the software barrier.
    int dev = 0, sms = 148, maxB = 1;
    cudaGetDevice(&dev);
    cudaDeviceGetAttribute(&sms, cudaDevAttrMultiProcessorCount, dev);
    cudaOccupancyMaxActiveBlocksPerMultiprocessor(&maxB, fused_kernel, 256, 0);
    if (maxB < 1) maxB = 1;
    long long cap = (long long)sms * maxB;
    long long ideal = (Bn + IPB - 1) / IPB; // 512 for Bn=32768
    long long grid = ideal;
    if (grid > cap)  grid = cap;
    if (grid > 1024) grid = 1024;           // g_partials capacity
    if (grid < 1)    grid = 1;

    fused_kernel<<<(int)grid, 256>>>(x, qw, w1, b1, w2, b2, gamma, beta,
                                     out, Bn);
}